// round 7
// baseline (speedup 1.0000x reference)
#include <cuda_runtime.h>
#include <cuda_bf16.h>
#include <cstdint>
#include <math.h>

#define BB 4
#define TT 2048
#define DM 512
#define HH 8
#define DH 64
#define MROWS (BB*TT)   // 8192
#define NBH (BB*HH)     // 32

// ---------------- scratch (__device__ globals; allocation-free) ----------------
__device__ float g_q[MROWS * DM];
__device__ float g_k[MROWS * DM];
__device__ float g_v[MROWS * DM];
__device__ float g_ctx[MROWS * DM];
__device__ float g_rowmax[NBH * TT];
__device__ float g_rowsum[NBH * TT];
__device__ float g_attn_fb[(size_t)NBH * TT * TT];  // fallback if d_out lacks attn

// ============================ helpers ============================
__device__ __forceinline__ void mma_bf16(float* c, const uint32_t* a, const uint32_t* b) {
    asm volatile(
        "mma.sync.aligned.m16n8k16.row.col.f32.bf16.bf16.f32 "
        "{%0,%1,%2,%3}, {%4,%5,%6,%7}, {%8,%9}, {%0,%1,%2,%3};"
        : "+f"(c[0]), "+f"(c[1]), "+f"(c[2]), "+f"(c[3])
        : "r"(a[0]), "r"(a[1]), "r"(a[2]), "r"(a[3]), "r"(b[0]), "r"(b[1]));
}

__device__ __forceinline__ void split2(float a, float b, uint32_t& hi, uint32_t& lo) {
    __nv_bfloat16 ha = __float2bfloat16(a), hb = __float2bfloat16(b);
    float ra = a - __bfloat162float(ha), rb = b - __bfloat162float(hb);
    __nv_bfloat16 la = __float2bfloat16(ra), lb = __float2bfloat16(rb);
    __nv_bfloat162 H; H.x = ha; H.y = hb;
    __nv_bfloat162 L; L.x = la; L.y = lb;
    hi = *(uint32_t*)&H; lo = *(uint32_t*)&L;
}

__device__ __forceinline__ uint32_t packbf(float a, float b) {
    __nv_bfloat162 H; H.x = __float2bfloat16(a); H.y = __float2bfloat16(b);
    return *(uint32_t*)&H;
}

// =============== proj_mma: Y = X @ W^T + b (M=8192, N=512, K=512) ===============
// CTA tile 128x128, 256 threads (8 warps, warp = 16-row strip x 128 cols).
// Smem rows: 64 bf16 padded to 72 el (36 words) -> conflict-free fragment LDS.
#define PJ_S 36
#define PJ_XHI 0
#define PJ_XLO 4608
#define PJ_WHI 9216
#define PJ_WLO 13824
#define PJ_BIAS 18432
#define PJ_SMEM_BYTES ((18432 + 128) * 4)

__global__ __launch_bounds__(256) void proj_mma(
    const float* __restrict__ X, const float* __restrict__ W,
    const float* __restrict__ bias, float* __restrict__ Y, int mode)
{
    extern __shared__ uint32_t sw[];
    const int tid = threadIdx.x;
    const int wid = tid >> 5, lane = tid & 31, g = lane >> 2, t4 = lane & 3;
    const int m0 = blockIdx.y * 128, n0 = blockIdx.x * 128;
    const int row = tid >> 1, half = tid & 1;
    const int strip = wid * 16;

    if (tid < 128) sw[PJ_BIAS + tid] = __float_as_uint(bias[n0 + tid]);

    float acc[16][4];
    #pragma unroll
    for (int j = 0; j < 16; j++) { acc[j][0] = acc[j][1] = acc[j][2] = acc[j][3] = 0.f; }

    for (int kc = 0; kc < 8; kc++) {
        const float* xp = X + (size_t)(m0 + row) * DM + kc * 64 + half * 32;
        const float* wp = W + (size_t)(n0 + row) * DM + kc * 64 + half * 32;
        #pragma unroll
        for (int c = 0; c < 4; c++) {
            float4 f0 = *(const float4*)(xp + c * 8);
            float4 f1 = *(const float4*)(xp + c * 8 + 4);
            uint4 HI, LO;
            split2(f0.x, f0.y, HI.x, LO.x); split2(f0.z, f0.w, HI.y, LO.y);
            split2(f1.x, f1.y, HI.z, LO.z); split2(f1.z, f1.w, HI.w, LO.w);
            int wo = row * PJ_S + half * 16 + c * 4;
            *(uint4*)&sw[PJ_XHI + wo] = HI; *(uint4*)&sw[PJ_XLO + wo] = LO;
            f0 = *(const float4*)(wp + c * 8);
            f1 = *(const float4*)(wp + c * 8 + 4);
            split2(f0.x, f0.y, HI.x, LO.x); split2(f0.z, f0.w, HI.y, LO.y);
            split2(f1.x, f1.y, HI.z, LO.z); split2(f1.z, f1.w, HI.w, LO.w);
            *(uint4*)&sw[PJ_WHI + wo] = HI; *(uint4*)&sw[PJ_WLO + wo] = LO;
        }
        __syncthreads();

        uint32_t ah[4][4], al[4][4];
        #pragma unroll
        for (int ks = 0; ks < 4; ks++) {
            int base = (strip + g) * PJ_S + ks * 8 + t4;
            ah[ks][0] = sw[PJ_XHI + base];
            ah[ks][1] = sw[PJ_XHI + base + 8 * PJ_S];
            ah[ks][2] = sw[PJ_XHI + base + 4];
            ah[ks][3] = sw[PJ_XHI + base + 8 * PJ_S + 4];
            al[ks][0] = sw[PJ_XLO + base];
            al[ks][1] = sw[PJ_XLO + base + 8 * PJ_S];
            al[ks][2] = sw[PJ_XLO + base + 4];
            al[ks][3] = sw[PJ_XLO + base + 8 * PJ_S + 4];
        }
        #pragma unroll
        for (int j = 0; j < 16; j++) {
            #pragma unroll
            for (int ks = 0; ks < 4; ks++) {
                int bb = (j * 8 + g) * PJ_S + ks * 8 + t4;
                uint32_t bh2[2] = { sw[PJ_WHI + bb], sw[PJ_WHI + bb + 4] };
                uint32_t bl2[2] = { sw[PJ_WLO + bb], sw[PJ_WLO + bb + 4] };
                mma_bf16(acc[j], ah[ks], bh2);
                mma_bf16(acc[j], ah[ks], bl2);
                mma_bf16(acc[j], al[ks], bh2);
            }
        }
        __syncthreads();
    }

    #pragma unroll
    for (int j = 0; j < 16; j++) {
        int nc = j * 8 + 2 * t4;
        int n = n0 + nc;
        float b0 = __uint_as_float(sw[PJ_BIAS + nc]);
        float b1 = __uint_as_float(sw[PJ_BIAS + nc + 1]);
        int r0 = m0 + strip + g, r1 = r0 + 8;
        float2 v0 = make_float2(acc[j][0] + b0, acc[j][1] + b1);
        float2 v1 = make_float2(acc[j][2] + b0, acc[j][3] + b1);
        if (mode == 0) {
            int h = n >> 6, d = n & 63;
            int b0i = r0 >> 11, t0i = r0 & 2047;
            int b1i = r1 >> 11, t1i = r1 & 2047;
            *(float2*)&Y[(((size_t)(b0i * HH + h) * TT) + t0i) * DH + d] = v0;
            *(float2*)&Y[(((size_t)(b1i * HH + h) * TT) + t1i) * DH + d] = v1;
        } else {
            *(float2*)&Y[(size_t)r0 * DM + n] = v0;
            *(float2*)&Y[(size_t)r1 * DM + n] = v1;
        }
    }
}

// =============== scores_mma: raw scores + per-row online softmax stats ===============
// grid (16 m-tiles, 32 bh), 256 threads. CTA: 128 rows x sweep 2048 keys in 128-chunks.
#define SC_S 36
#define SC_QHI 0
#define SC_QLO 4608
#define SC_KHI 9216
#define SC_KLO 13824
#define SC_SMEM_BYTES (18432 * 4)

__global__ __launch_bounds__(256) void scores_mma(
    const float* __restrict__ q, const float* __restrict__ k,
    float* __restrict__ attn, float* __restrict__ rmax, float* __restrict__ rsum)
{
    extern __shared__ uint32_t sw[];
    const int tid = threadIdx.x;
    const int wid = tid >> 5, lane = tid & 31, g = lane >> 2, t4 = lane & 3;
    const int bh = blockIdx.y, m0 = blockIdx.x * 128;
    const int row = tid >> 1, half = tid & 1;
    const int strip = wid * 16;

    // Q tile: scale by 1/8, split hi/lo
    {
        const float* qp = q + ((size_t)bh * TT + m0 + row) * DH + half * 32;
        #pragma unroll
        for (int c = 0; c < 4; c++) {
            float4 f0 = *(const float4*)(qp + c * 8);
            float4 f1 = *(const float4*)(qp + c * 8 + 4);
            f0.x *= 0.125f; f0.y *= 0.125f; f0.z *= 0.125f; f0.w *= 0.125f;
            f1.x *= 0.125f; f1.y *= 0.125f; f1.z *= 0.125f; f1.w *= 0.125f;
            uint4 HI, LO;
            split2(f0.x, f0.y, HI.x, LO.x); split2(f0.z, f0.w, HI.y, LO.y);
            split2(f1.x, f1.y, HI.z, LO.z); split2(f1.z, f1.w, HI.w, LO.w);
            int wo = row * SC_S + half * 16 + c * 4;
            *(uint4*)&sw[SC_QHI + wo] = HI; *(uint4*)&sw[SC_QLO + wo] = LO;
        }
    }
    __syncthreads();

    uint32_t ah[4][4], al[4][4];
    #pragma unroll
    for (int ks = 0; ks < 4; ks++) {
        int base = (strip + g) * SC_S + ks * 8 + t4;
        ah[ks][0] = sw[SC_QHI + base];
        ah[ks][1] = sw[SC_QHI + base + 8 * SC_S];
        ah[ks][2] = sw[SC_QHI + base + 4];
        ah[ks][3] = sw[SC_QHI + base + 8 * SC_S + 4];
        al[ks][0] = sw[SC_QLO + base];
        al[ks][1] = sw[SC_QLO + base + 8 * SC_S];
        al[ks][2] = sw[SC_QLO + base + 4];
        al[ks][3] = sw[SC_QLO + base + 8 * SC_S + 4];
    }

    float runM0 = -1e30f, runM1 = -1e30f, runS0 = 0.f, runS1 = 0.f;
    const int r0 = m0 + strip + g, r1 = r0 + 8;
    float* arow0 = attn + ((size_t)bh * TT + r0) * TT;
    float* arow1 = attn + ((size_t)bh * TT + r1) * TT;

    for (int nt = 0; nt < 16; nt++) {
        // K chunk -> smem hi/lo
        {
            const float* kp = k + ((size_t)bh * TT + nt * 128 + row) * DH + half * 32;
            #pragma unroll
            for (int c = 0; c < 4; c++) {
                float4 f0 = *(const float4*)(kp + c * 8);
                float4 f1 = *(const float4*)(kp + c * 8 + 4);
                uint4 HI, LO;
                split2(f0.x, f0.y, HI.x, LO.x); split2(f0.z, f0.w, HI.y, LO.y);
                split2(f1.x, f1.y, HI.z, LO.z); split2(f1.z, f1.w, HI.w, LO.w);
                int wo = row * SC_S + half * 16 + c * 4;
                *(uint4*)&sw[SC_KHI + wo] = HI; *(uint4*)&sw[SC_KLO + wo] = LO;
            }
        }
        __syncthreads();

        float acc[16][4];
        #pragma unroll
        for (int j = 0; j < 16; j++) { acc[j][0] = acc[j][1] = acc[j][2] = acc[j][3] = 0.f; }
        #pragma unroll
        for (int j = 0; j < 16; j++) {
            #pragma unroll
            for (int ks = 0; ks < 4; ks++) {
                int bb = (j * 8 + g) * SC_S + ks * 8 + t4;
                uint32_t bh2[2] = { sw[SC_KHI + bb], sw[SC_KHI + bb + 4] };
                uint32_t bl2[2] = { sw[SC_KLO + bb], sw[SC_KLO + bb + 4] };
                mma_bf16(acc[j], ah[ks], bh2);
                mma_bf16(acc[j], ah[ks], bl2);
                mma_bf16(acc[j], al[ks], bh2);
            }
        }

        // online softmax stats (row = quad of lanes)
        float cm0 = -1e30f, cm1 = -1e30f;
        #pragma unroll
        for (int j = 0; j < 16; j++) {
            cm0 = fmaxf(cm0, fmaxf(acc[j][0], acc[j][1]));
            cm1 = fmaxf(cm1, fmaxf(acc[j][2], acc[j][3]));
        }
        cm0 = fmaxf(cm0, __shfl_xor_sync(0xffffffffu, cm0, 1));
        cm0 = fmaxf(cm0, __shfl_xor_sync(0xffffffffu, cm0, 2));
        cm1 = fmaxf(cm1, __shfl_xor_sync(0xffffffffu, cm1, 1));
        cm1 = fmaxf(cm1, __shfl_xor_sync(0xffffffffu, cm1, 2));
        float nM0 = fmaxf(runM0, cm0), nM1 = fmaxf(runM1, cm1);
        float add0 = 0.f, add1 = 0.f;
        #pragma unroll
        for (int j = 0; j < 16; j++) {
            add0 += __expf(acc[j][0] - nM0) + __expf(acc[j][1] - nM0);
            add1 += __expf(acc[j][2] - nM1) + __expf(acc[j][3] - nM1);
        }
        runS0 = runS0 * __expf(runM0 - nM0) + add0; runM0 = nM0;
        runS1 = runS1 * __expf(runM1 - nM1) + add1; runM1 = nM1;

        // raw store
        #pragma unroll
        for (int j = 0; j < 16; j++) {
            int nc = nt * 128 + j * 8 + 2 * t4;
            *(float2*)&arow0[nc] = make_float2(acc[j][0], acc[j][1]);
            *(float2*)&arow1[nc] = make_float2(acc[j][2], acc[j][3]);
        }
        __syncthreads();
    }

    runS0 += __shfl_xor_sync(0xffffffffu, runS0, 1);
    runS0 += __shfl_xor_sync(0xffffffffu, runS0, 2);
    runS1 += __shfl_xor_sync(0xffffffffu, runS1, 1);
    runS1 += __shfl_xor_sync(0xffffffffu, runS1, 2);
    if (t4 == 0) {
        rmax[bh * TT + r0] = runM0; rsum[bh * TT + r0] = runS0;
        rmax[bh * TT + r1] = runM1; rsum[bh * TT + r1] = runS1;
    }
}

// =============== ctx_mma: normalize attn in place + P@V (HMMA) ===============
// grid (16 m-tiles, 32 bh), 256 threads. K sweep 2048 in 128-chunks, N=64.
#define CT_S 68
#define CT_PHI 0
#define CT_PLO 8704
#define CT_VTHI 17408
#define CT_VTLO 21760
#define CT_VST 26112
#define CT_SMEM_BYTES (34816 * 4)

__global__ __launch_bounds__(256) void ctx_mma(
    float* __restrict__ attn, const float* __restrict__ v,
    float* __restrict__ ctx,
    const float* __restrict__ rmax, const float* __restrict__ rsum)
{
    extern __shared__ uint32_t sw[];
    const int tid = threadIdx.x;
    const int wid = tid >> 5, lane = tid & 31, g = lane >> 2, t4 = lane & 3;
    const int bh = blockIdx.y, m0 = blockIdx.x * 128;
    const int b_ = bh >> 3, h = bh & 7;
    const int row = tid >> 1, half = tid & 1;
    const int strip = wid * 16;
    const int dcol = tid & 63, kseg = tid >> 6;

    const float Mr = rmax[bh * TT + m0 + row];
    const float inv = 1.f / rsum[bh * TT + m0 + row];

    float acc[8][4];
    #pragma unroll
    for (int j = 0; j < 8; j++) { acc[j][0] = acc[j][1] = acc[j][2] = acc[j][3] = 0.f; }

    for (int kt = 0; kt < 16; kt++) {
        // P: normalize in place, split hi/lo to smem
        {
            float* ap = attn + ((size_t)bh * TT + m0 + row) * TT + kt * 128 + half * 64;
            #pragma unroll
            for (int c = 0; c < 8; c++) {
                float4 f0 = *(const float4*)(ap + c * 8);
                float4 f1 = *(const float4*)(ap + c * 8 + 4);
                f0.x = __expf(f0.x - Mr) * inv; f0.y = __expf(f0.y - Mr) * inv;
                f0.z = __expf(f0.z - Mr) * inv; f0.w = __expf(f0.w - Mr) * inv;
                f1.x = __expf(f1.x - Mr) * inv; f1.y = __expf(f1.y - Mr) * inv;
                f1.z = __expf(f1.z - Mr) * inv; f1.w = __expf(f1.w - Mr) * inv;
                *(float4*)(ap + c * 8) = f0;
                *(float4*)(ap + c * 8 + 4) = f1;
                uint4 HI, LO;
                split2(f0.x, f0.y, HI.x, LO.x); split2(f0.z, f0.w, HI.y, LO.y);
                split2(f1.x, f1.y, HI.z, LO.z); split2(f1.z, f1.w, HI.w, LO.w);
                int wo = row * CT_S + half * 32 + c * 4;
                *(uint4*)&sw[CT_PHI + wo] = HI; *(uint4*)&sw[CT_PLO + wo] = LO;
            }
        }
        // V: stage to smem (float, row-major [k][d])
        {
            const float* vp = v + ((size_t)bh * TT + kt * 128 + row) * DH + half * 32;
            #pragma unroll
            for (int c = 0; c < 8; c++) {
                float4 f = *(const float4*)(vp + c * 4);
                *(float4*)&sw[CT_VST + row * CT_S + half * 32 + c * 4] = f;
            }
        }
        __syncthreads();
        // transpose+convert: VT[d][k] bf16 hi/lo
        #pragma unroll
        for (int kk = 0; kk < 32; kk += 2) {
            int k0 = kseg * 32 + kk;
            float v0 = __uint_as_float(sw[CT_VST + k0 * CT_S + dcol]);
            float v1 = __uint_as_float(sw[CT_VST + (k0 + 1) * CT_S + dcol]);
            __nv_bfloat16 h0 = __float2bfloat16(v0), h1 = __float2bfloat16(v1);
            float rr0 = v0 - __bfloat162float(h0), rr1 = v1 - __bfloat162float(h1);
            uint32_t hw = packbf(__bfloat162float(h0), __bfloat162float(h1));
            uint32_t lw = packbf(rr0, rr1);
            int wo = dcol * CT_S + k0 / 2;
            sw[CT_VTHI + wo] = hw; sw[CT_VTLO + wo] = lw;
        }
        __syncthreads();

        #pragma unroll
        for (int ks = 0; ks < 8; ks++) {
            uint32_t ah2[4], al2[4];
            int base = (strip + g) * CT_S + ks * 8 + t4;
            ah2[0] = sw[CT_PHI + base];
            ah2[1] = sw[CT_PHI + base + 8 * CT_S];
            ah2[2] = sw[CT_PHI + base + 4];
            ah2[3] = sw[CT_PHI + base + 8 * CT_S + 4];
            al2[0] = sw[CT_PLO + base];
            al2[1] = sw[CT_PLO + base + 8 * CT_S];
            al2[2] = sw[CT_PLO + base + 4];
            al2[3] = sw[CT_PLO + base + 8 * CT_S + 4];
            #pragma unroll
            for (int j = 0; j < 8; j++) {
                int bb = (j * 8 + g) * CT_S + ks * 8 + t4;
                uint32_t bh2[2] = { sw[CT_VTHI + bb], sw[CT_VTHI + bb + 4] };
                uint32_t bl2[2] = { sw[CT_VTLO + bb], sw[CT_VTLO + bb + 4] };
                mma_bf16(acc[j], ah2, bh2);
                mma_bf16(acc[j], ah2, bl2);
                mma_bf16(acc[j], al2, bh2);
            }
        }
        __syncthreads();
    }

    const int r0 = m0 + strip + g, r1 = r0 + 8;
    float* c0p = ctx + ((size_t)(b_ * TT + r0)) * DM + h * DH;
    float* c1p = ctx + ((size_t)(b_ * TT + r1)) * DM + h * DH;
    #pragma unroll
    for (int j = 0; j < 8; j++) {
        int d = j * 8 + 2 * t4;
        *(float2*)&c0p[d] = make_float2(acc[j][0], acc[j][1]);
        *(float2*)&c1p[d] = make_float2(acc[j][2], acc[j][3]);
    }
}

// ---------------- launch ----------------
extern "C" void kernel_launch(void* const* d_in, const int* in_sizes, int n_in,
                              void* d_out, int out_size)
{
    const float* Q  = (const float*)d_in[0];
    const float* K  = (const float*)d_in[1];
    const float* V  = (const float*)d_in[2];
    const float* Wq = (const float*)d_in[3];
    const float* bq = (const float*)d_in[4];
    const float* Wk = (const float*)d_in[5];
    const float* bk = (const float*)d_in[6];
    const float* Wv = (const float*)d_in[7];
    const float* bv = (const float*)d_in[8];
    const float* Wo = (const float*)d_in[9];
    const float* bo = (const float*)d_in[10];

    float* out = (float*)d_out;
    const long long OUT_ELEMS  = (long long)BB * TT * DM;
    const long long ATTN_ELEMS = (long long)NBH * TT * TT;

    float *q, *k, *v, *ctx, *attn, *rmax, *rsum;
    { void* p; cudaGetSymbolAddress(&p, g_q);      q    = (float*)p; }
    { void* p; cudaGetSymbolAddress(&p, g_k);      k    = (float*)p; }
    { void* p; cudaGetSymbolAddress(&p, g_v);      v    = (float*)p; }
    { void* p; cudaGetSymbolAddress(&p, g_ctx);    ctx  = (float*)p; }
    { void* p; cudaGetSymbolAddress(&p, g_rowmax); rmax = (float*)p; }
    { void* p; cudaGetSymbolAddress(&p, g_rowsum); rsum = (float*)p; }
    if ((long long)out_size >= OUT_ELEMS + ATTN_ELEMS) {
        attn = out + OUT_ELEMS;
    } else {
        void* p; cudaGetSymbolAddress(&p, g_attn_fb); attn = (float*)p;
    }

    cudaFuncSetAttribute(proj_mma,   cudaFuncAttributeMaxDynamicSharedMemorySize, PJ_SMEM_BYTES);
    cudaFuncSetAttribute(scores_mma, cudaFuncAttributeMaxDynamicSharedMemorySize, SC_SMEM_BYTES);
    cudaFuncSetAttribute(ctx_mma,    cudaFuncAttributeMaxDynamicSharedMemorySize, CT_SMEM_BYTES);

    dim3 gp(DM / 128, MROWS / 128);   // (4, 64)
    proj_mma<<<gp, 256, PJ_SMEM_BYTES>>>(Q, Wq, bq, q, 0);
    proj_mma<<<gp, 256, PJ_SMEM_BYTES>>>(K, Wk, bk, k, 0);
    proj_mma<<<gp, 256, PJ_SMEM_BYTES>>>(V, Wv, bv, v, 0);

    dim3 gs(TT / 128, NBH);           // (16, 32)
    scores_mma<<<gs, 256, SC_SMEM_BYTES>>>(q, k, attn, rmax, rsum);
    ctx_mma<<<gs, 256, CT_SMEM_BYTES>>>(attn, v, ctx, rmax, rsum);

    proj_mma<<<gp, 256, PJ_SMEM_BYTES>>>(ctx, Wo, bo, out, 1);
}

// round 8
// speedup vs baseline: 2.4546x; 2.4546x over previous
#include <cuda_runtime.h>
#include <cuda_bf16.h>
#include <cstdint>
#include <math.h>

#define BB 4
#define TT 2048
#define DM 512
#define HH 8
#define DH 64
#define MROWS (BB*TT)   // 8192
#define NBH (BB*HH)     // 32

// ---------------- scratch (__device__ globals; allocation-free) ----------------
__device__ float g_q[MROWS * DM];
__device__ float g_k[MROWS * DM];
__device__ float g_v[MROWS * DM];
__device__ float g_ctx[MROWS * DM];
__device__ float g_rowmax[NBH * TT];
__device__ float g_rowsum[NBH * TT];
__device__ float g_attn_fb[(size_t)NBH * TT * TT];  // fallback if d_out lacks attn

// ============================ helpers ============================
__device__ __forceinline__ void mma_bf16(float* c, const uint32_t* a, const uint32_t* b) {
    asm volatile(
        "mma.sync.aligned.m16n8k16.row.col.f32.bf16.bf16.f32 "
        "{%0,%1,%2,%3}, {%4,%5,%6,%7}, {%8,%9}, {%0,%1,%2,%3};"
        : "+f"(c[0]), "+f"(c[1]), "+f"(c[2]), "+f"(c[3])
        : "r"(a[0]), "r"(a[1]), "r"(a[2]), "r"(a[3]), "r"(b[0]), "r"(b[1]));
}

__device__ __forceinline__ void split2(float a, float b, uint32_t& hi, uint32_t& lo) {
    __nv_bfloat16 ha = __float2bfloat16(a), hb = __float2bfloat16(b);
    float ra = a - __bfloat162float(ha), rb = b - __bfloat162float(hb);
    __nv_bfloat16 la = __float2bfloat16(ra), lb = __float2bfloat16(rb);
    __nv_bfloat162 H; H.x = ha; H.y = hb;
    __nv_bfloat162 L; L.x = la; L.y = lb;
    hi = *(uint32_t*)&H; lo = *(uint32_t*)&L;
}

__device__ __forceinline__ uint32_t packbf(float a, float b) {
    __nv_bfloat162 H; H.x = __float2bfloat16(a); H.y = __float2bfloat16(b);
    return *(uint32_t*)&H;
}

// =============== proj_mma: Y = X @ W^T + b (M=8192, N=512, K=512) ===============
// CTA tile 128x128, 512 threads (16 warps; warp = 16 rows x 64 cols; acc 32 regs).
#define PJ_S 36
#define PJ_XHI 0
#define PJ_XLO 4608
#define PJ_WHI 9216
#define PJ_WLO 13824
#define PJ_BIAS 18432
#define PJ_SMEM_BYTES ((18432 + 128) * 4)

__global__ __launch_bounds__(512) void proj_mma(
    const float* __restrict__ X, const float* __restrict__ W,
    const float* __restrict__ bias, float* __restrict__ Y, int mode)
{
    extern __shared__ uint32_t sw[];
    const int tid = threadIdx.x;
    const int wid = tid >> 5, lane = tid & 31, g = lane >> 2, t4 = lane & 3;
    const int wr = wid >> 1, wc = wid & 1;        // row strip 0..7, col half 0..1
    const int strip = wr * 16, colb = wc * 64;
    const int m0 = blockIdx.y * 128, n0 = blockIdx.x * 128;
    const int row = tid >> 2, q = tid & 3;        // loader: row 0..127, quarter 0..3

    if (tid < 128) sw[PJ_BIAS + tid] = __float_as_uint(bias[n0 + tid]);

    float acc[8][4];
    #pragma unroll
    for (int j = 0; j < 8; j++) { acc[j][0] = acc[j][1] = acc[j][2] = acc[j][3] = 0.f; }

    for (int kc = 0; kc < 8; kc++) {
        const float* xp = X + (size_t)(m0 + row) * DM + kc * 64 + q * 16;
        const float* wp = W + (size_t)(n0 + row) * DM + kc * 64 + q * 16;
        #pragma unroll
        for (int c = 0; c < 2; c++) {
            float4 f0 = *(const float4*)(xp + c * 8);
            float4 f1 = *(const float4*)(xp + c * 8 + 4);
            uint4 HI, LO;
            split2(f0.x, f0.y, HI.x, LO.x); split2(f0.z, f0.w, HI.y, LO.y);
            split2(f1.x, f1.y, HI.z, LO.z); split2(f1.z, f1.w, HI.w, LO.w);
            int wo = row * PJ_S + q * 8 + c * 4;
            *(uint4*)&sw[PJ_XHI + wo] = HI; *(uint4*)&sw[PJ_XLO + wo] = LO;
            f0 = *(const float4*)(wp + c * 8);
            f1 = *(const float4*)(wp + c * 8 + 4);
            split2(f0.x, f0.y, HI.x, LO.x); split2(f0.z, f0.w, HI.y, LO.y);
            split2(f1.x, f1.y, HI.z, LO.z); split2(f1.z, f1.w, HI.w, LO.w);
            *(uint4*)&sw[PJ_WHI + wo] = HI; *(uint4*)&sw[PJ_WLO + wo] = LO;
        }
        __syncthreads();

        #pragma unroll
        for (int ks = 0; ks < 4; ks++) {
            uint32_t ah[4], al[4];
            int base = (strip + g) * PJ_S + ks * 8 + t4;
            ah[0] = sw[PJ_XHI + base];
            ah[1] = sw[PJ_XHI + base + 8 * PJ_S];
            ah[2] = sw[PJ_XHI + base + 4];
            ah[3] = sw[PJ_XHI + base + 8 * PJ_S + 4];
            al[0] = sw[PJ_XLO + base];
            al[1] = sw[PJ_XLO + base + 8 * PJ_S];
            al[2] = sw[PJ_XLO + base + 4];
            al[3] = sw[PJ_XLO + base + 8 * PJ_S + 4];
            #pragma unroll
            for (int j = 0; j < 8; j++) {
                int bb = (colb + j * 8 + g) * PJ_S + ks * 8 + t4;
                uint32_t bh2[2] = { sw[PJ_WHI + bb], sw[PJ_WHI + bb + 4] };
                uint32_t bl2[2] = { sw[PJ_WLO + bb], sw[PJ_WLO + bb + 4] };
                mma_bf16(acc[j], ah, bh2);
                mma_bf16(acc[j], ah, bl2);
                mma_bf16(acc[j], al, bh2);
            }
        }
        __syncthreads();
    }

    #pragma unroll
    for (int j = 0; j < 8; j++) {
        int nc = colb + j * 8 + 2 * t4;
        int n = n0 + nc;
        float b0 = __uint_as_float(sw[PJ_BIAS + nc]);
        float b1 = __uint_as_float(sw[PJ_BIAS + nc + 1]);
        int r0 = m0 + strip + g, r1 = r0 + 8;
        float2 v0 = make_float2(acc[j][0] + b0, acc[j][1] + b1);
        float2 v1 = make_float2(acc[j][2] + b0, acc[j][3] + b1);
        if (mode == 0) {
            int h = n >> 6, d = n & 63;
            int b0i = r0 >> 11, t0i = r0 & 2047;
            int b1i = r1 >> 11, t1i = r1 & 2047;
            *(float2*)&Y[(((size_t)(b0i * HH + h) * TT) + t0i) * DH + d] = v0;
            *(float2*)&Y[(((size_t)(b1i * HH + h) * TT) + t1i) * DH + d] = v1;
        } else {
            *(float2*)&Y[(size_t)r0 * DM + n] = v0;
            *(float2*)&Y[(size_t)r1 * DM + n] = v1;
        }
    }
}

// =============== scores_mma: raw scores + per-row online softmax stats ===============
// grid (16 m-tiles, 32 bh), 512 threads. Warp = 16 rows x 64 of each 128-key chunk.
#define SC_S 36
#define SC_QHI 0
#define SC_QLO 4608
#define SC_KHI 9216
#define SC_KLO 13824
#define SC_SMEM_BYTES (18432 * 4)

__global__ __launch_bounds__(512) void scores_mma(
    const float* __restrict__ q, const float* __restrict__ k,
    float* __restrict__ attn, float* __restrict__ rmax, float* __restrict__ rsum)
{
    extern __shared__ uint32_t sw[];
    const int tid = threadIdx.x;
    const int wid = tid >> 5, lane = tid & 31, g = lane >> 2, t4 = lane & 3;
    const int wr = wid >> 1, wc = wid & 1;
    const int strip = wr * 16, colb = wc * 64;
    const int bh = blockIdx.y, m0 = blockIdx.x * 128;
    const int row = tid >> 2, qq = tid & 3;

    // Q tile: scale by 1/8, split hi/lo
    {
        const float* qp = q + ((size_t)bh * TT + m0 + row) * DH + qq * 16;
        #pragma unroll
        for (int c = 0; c < 2; c++) {
            float4 f0 = *(const float4*)(qp + c * 8);
            float4 f1 = *(const float4*)(qp + c * 8 + 4);
            f0.x *= 0.125f; f0.y *= 0.125f; f0.z *= 0.125f; f0.w *= 0.125f;
            f1.x *= 0.125f; f1.y *= 0.125f; f1.z *= 0.125f; f1.w *= 0.125f;
            uint4 HI, LO;
            split2(f0.x, f0.y, HI.x, LO.x); split2(f0.z, f0.w, HI.y, LO.y);
            split2(f1.x, f1.y, HI.z, LO.z); split2(f1.z, f1.w, HI.w, LO.w);
            int wo = row * SC_S + qq * 8 + c * 4;
            *(uint4*)&sw[SC_QHI + wo] = HI; *(uint4*)&sw[SC_QLO + wo] = LO;
        }
    }
    __syncthreads();

    uint32_t ah[4][4], al[4][4];
    #pragma unroll
    for (int ks = 0; ks < 4; ks++) {
        int base = (strip + g) * SC_S + ks * 8 + t4;
        ah[ks][0] = sw[SC_QHI + base];
        ah[ks][1] = sw[SC_QHI + base + 8 * SC_S];
        ah[ks][2] = sw[SC_QHI + base + 4];
        ah[ks][3] = sw[SC_QHI + base + 8 * SC_S + 4];
        al[ks][0] = sw[SC_QLO + base];
        al[ks][1] = sw[SC_QLO + base + 8 * SC_S];
        al[ks][2] = sw[SC_QLO + base + 4];
        al[ks][3] = sw[SC_QLO + base + 8 * SC_S + 4];
    }

    float runM0 = -1e30f, runM1 = -1e30f, runS0 = 0.f, runS1 = 0.f;
    const int r0 = m0 + strip + g, r1 = r0 + 8;
    float* arow0 = attn + ((size_t)bh * TT + r0) * TT;
    float* arow1 = attn + ((size_t)bh * TT + r1) * TT;

    for (int nt = 0; nt < 16; nt++) {
        // K chunk -> smem hi/lo
        {
            const float* kp = k + ((size_t)bh * TT + nt * 128 + row) * DH + qq * 16;
            #pragma unroll
            for (int c = 0; c < 2; c++) {
                float4 f0 = *(const float4*)(kp + c * 8);
                float4 f1 = *(const float4*)(kp + c * 8 + 4);
                uint4 HI, LO;
                split2(f0.x, f0.y, HI.x, LO.x); split2(f0.z, f0.w, HI.y, LO.y);
                split2(f1.x, f1.y, HI.z, LO.z); split2(f1.z, f1.w, HI.w, LO.w);
                int wo = row * SC_S + qq * 8 + c * 4;
                *(uint4*)&sw[SC_KHI + wo] = HI; *(uint4*)&sw[SC_KLO + wo] = LO;
            }
        }
        __syncthreads();

        float acc[8][4];
        #pragma unroll
        for (int j = 0; j < 8; j++) { acc[j][0] = acc[j][1] = acc[j][2] = acc[j][3] = 0.f; }
        #pragma unroll
        for (int ks = 0; ks < 4; ks++) {
            #pragma unroll
            for (int j = 0; j < 8; j++) {
                int bb = (colb + j * 8 + g) * SC_S + ks * 8 + t4;
                uint32_t bh2[2] = { sw[SC_KHI + bb], sw[SC_KHI + bb + 4] };
                uint32_t bl2[2] = { sw[SC_KLO + bb], sw[SC_KLO + bb + 4] };
                mma_bf16(acc[j], ah[ks], bh2);
                mma_bf16(acc[j], ah[ks], bl2);
                mma_bf16(acc[j], al[ks], bh2);
            }
        }

        // online stats over this warp's 64 cols (rows = lane quads)
        float cm0 = -1e30f, cm1 = -1e30f;
        #pragma unroll
        for (int j = 0; j < 8; j++) {
            cm0 = fmaxf(cm0, fmaxf(acc[j][0], acc[j][1]));
            cm1 = fmaxf(cm1, fmaxf(acc[j][2], acc[j][3]));
        }
        cm0 = fmaxf(cm0, __shfl_xor_sync(0xffffffffu, cm0, 1));
        cm0 = fmaxf(cm0, __shfl_xor_sync(0xffffffffu, cm0, 2));
        cm1 = fmaxf(cm1, __shfl_xor_sync(0xffffffffu, cm1, 1));
        cm1 = fmaxf(cm1, __shfl_xor_sync(0xffffffffu, cm1, 2));
        float nM0 = fmaxf(runM0, cm0), nM1 = fmaxf(runM1, cm1);
        float add0 = 0.f, add1 = 0.f;
        #pragma unroll
        for (int j = 0; j < 8; j++) {
            add0 += __expf(acc[j][0] - nM0) + __expf(acc[j][1] - nM0);
            add1 += __expf(acc[j][2] - nM1) + __expf(acc[j][3] - nM1);
        }
        runS0 = runS0 * __expf(runM0 - nM0) + add0; runM0 = nM0;
        runS1 = runS1 * __expf(runM1 - nM1) + add1; runM1 = nM1;

        // raw store
        #pragma unroll
        for (int j = 0; j < 8; j++) {
            int nc = nt * 128 + colb + j * 8 + 2 * t4;
            *(float2*)&arow0[nc] = make_float2(acc[j][0], acc[j][1]);
            *(float2*)&arow1[nc] = make_float2(acc[j][2], acc[j][3]);
        }
        __syncthreads();
    }

    // combine warp-pair halves through smem (reuse SC_QHI region)
    runS0 += __shfl_xor_sync(0xffffffffu, runS0, 1);
    runS0 += __shfl_xor_sync(0xffffffffu, runS0, 2);
    runS1 += __shfl_xor_sync(0xffffffffu, runS1, 1);
    runS1 += __shfl_xor_sync(0xffffffffu, runS1, 2);
    float* sM = (float*)&sw[SC_QHI];          // [128][2]
    float* sS = (float*)&sw[SC_QHI + 256];    // [128][2]
    if (t4 == 0) {
        sM[(strip + g) * 2 + wc] = runM0; sS[(strip + g) * 2 + wc] = runS0;
        sM[(strip + g + 8) * 2 + wc] = runM1; sS[(strip + g + 8) * 2 + wc] = runS1;
    }
    __syncthreads();
    if (tid < 128) {
        float M0 = sM[tid * 2], M1 = sM[tid * 2 + 1];
        float M = fmaxf(M0, M1);
        float S = sS[tid * 2] * __expf(M0 - M) + sS[tid * 2 + 1] * __expf(M1 - M);
        rmax[bh * TT + m0 + tid] = M;
        rsum[bh * TT + m0 + tid] = S;
    }
}

// =============== ctx_mma: normalize attn in place + P@V (HMMA) ===============
// grid (16 m-tiles, 32 bh), 512 threads. Warp = 16 rows x 32 d-cols; acc 16 regs.
#define CT_S 68
#define CT_PHI 0
#define CT_PLO 8704
#define CT_VTHI 17408
#define CT_VTLO 21760
#define CT_VST 26112
#define CT_SMEM_BYTES (34816 * 4)

__global__ __launch_bounds__(512) void ctx_mma(
    float* __restrict__ attn, const float* __restrict__ v,
    float* __restrict__ ctx,
    const float* __restrict__ rmax, const float* __restrict__ rsum)
{
    extern __shared__ uint32_t sw[];
    const int tid = threadIdx.x;
    const int wid = tid >> 5, lane = tid & 31, g = lane >> 2, t4 = lane & 3;
    const int wr = wid >> 1, wc = wid & 1;
    const int strip = wr * 16, colb = wc * 32;
    const int bh = blockIdx.y, m0 = blockIdx.x * 128;
    const int b_ = bh >> 3, h = bh & 7;
    const int row = tid >> 2, qq = tid & 3;
    const int dcol = tid & 63, kseg = tid >> 6;   // transpose mapping (8 segs x 16 k)

    const float Mr = rmax[bh * TT + m0 + row];
    const float inv = 1.f / rsum[bh * TT + m0 + row];

    float acc[4][4];
    #pragma unroll
    for (int j = 0; j < 4; j++) { acc[j][0] = acc[j][1] = acc[j][2] = acc[j][3] = 0.f; }

    for (int kt = 0; kt < 16; kt++) {
        // P: normalize in place, split hi/lo to smem (thread: row, 32-col quarter)
        {
            float* ap = attn + ((size_t)bh * TT + m0 + row) * TT + kt * 128 + qq * 32;
            #pragma unroll
            for (int c = 0; c < 4; c++) {
                float4 f0 = *(const float4*)(ap + c * 8);
                float4 f1 = *(const float4*)(ap + c * 8 + 4);
                f0.x = __expf(f0.x - Mr) * inv; f0.y = __expf(f0.y - Mr) * inv;
                f0.z = __expf(f0.z - Mr) * inv; f0.w = __expf(f0.w - Mr) * inv;
                f1.x = __expf(f1.x - Mr) * inv; f1.y = __expf(f1.y - Mr) * inv;
                f1.z = __expf(f1.z - Mr) * inv; f1.w = __expf(f1.w - Mr) * inv;
                *(float4*)(ap + c * 8) = f0;
                *(float4*)(ap + c * 8 + 4) = f1;
                uint4 HI, LO;
                split2(f0.x, f0.y, HI.x, LO.x); split2(f0.z, f0.w, HI.y, LO.y);
                split2(f1.x, f1.y, HI.z, LO.z); split2(f1.z, f1.w, HI.w, LO.w);
                int wo = row * CT_S + qq * 16 + c * 4;
                *(uint4*)&sw[CT_PHI + wo] = HI; *(uint4*)&sw[CT_PLO + wo] = LO;
            }
        }
        // V: stage to smem (float, row-major [k][d]); thread: row, 16-float quarter
        {
            const float* vp = v + ((size_t)bh * TT + kt * 128 + row) * DH + qq * 16;
            #pragma unroll
            for (int c = 0; c < 4; c++) {
                float4 f = *(const float4*)(vp + c * 4);
                *(float4*)&sw[CT_VST + row * CT_S + qq * 16 + c * 4] = f;
            }
        }
        __syncthreads();
        // transpose+convert: VT[d][k] bf16 hi/lo
        #pragma unroll
        for (int kk = 0; kk < 16; kk += 2) {
            int k0 = kseg * 16 + kk;
            float v0 = __uint_as_float(sw[CT_VST + k0 * CT_S + dcol]);
            float v1 = __uint_as_float(sw[CT_VST + (k0 + 1) * CT_S + dcol]);
            __nv_bfloat16 h0 = __float2bfloat16(v0), h1 = __float2bfloat16(v1);
            float rr0 = v0 - __bfloat162float(h0), rr1 = v1 - __bfloat162float(h1);
            uint32_t hw = packbf(__bfloat162float(h0), __bfloat162float(h1));
            uint32_t lw = packbf(rr0, rr1);
            int wo = dcol * CT_S + k0 / 2;
            sw[CT_VTHI + wo] = hw; sw[CT_VTLO + wo] = lw;
        }
        __syncthreads();

        #pragma unroll
        for (int ks = 0; ks < 8; ks++) {
            uint32_t ah2[4], al2[4];
            int base = (strip + g) * CT_S + ks * 8 + t4;
            ah2[0] = sw[CT_PHI + base];
            ah2[1] = sw[CT_PHI + base + 8 * CT_S];
            ah2[2] = sw[CT_PHI + base + 4];
            ah2[3] = sw[CT_PHI + base + 8 * CT_S + 4];
            al2[0] = sw[CT_PLO + base];
            al2[1] = sw[CT_PLO + base + 8 * CT_S];
            al2[2] = sw[CT_PLO + base + 4];
            al2[3] = sw[CT_PLO + base + 8 * CT_S + 4];
            #pragma unroll
            for (int j = 0; j < 4; j++) {
                int bb = (colb + j * 8 + g) * CT_S + ks * 8 + t4;
                uint32_t bh2[2] = { sw[CT_VTHI + bb], sw[CT_VTHI + bb + 4] };
                uint32_t bl2[2] = { sw[CT_VTLO + bb], sw[CT_VTLO + bb + 4] };
                mma_bf16(acc[j], ah2, bh2);
                mma_bf16(acc[j], ah2, bl2);
                mma_bf16(acc[j], al2, bh2);
            }
        }
        __syncthreads();
    }

    const int r0 = m0 + strip + g, r1 = r0 + 8;
    float* c0p = ctx + ((size_t)(b_ * TT + r0)) * DM + h * DH;
    float* c1p = ctx + ((size_t)(b_ * TT + r1)) * DM + h * DH;
    #pragma unroll
    for (int j = 0; j < 4; j++) {
        int d = colb + j * 8 + 2 * t4;
        *(float2*)&c0p[d] = make_float2(acc[j][0], acc[j][1]);
        *(float2*)&c1p[d] = make_float2(acc[j][2], acc[j][3]);
    }
}

// ---------------- launch ----------------
extern "C" void kernel_launch(void* const* d_in, const int* in_sizes, int n_in,
                              void* d_out, int out_size)
{
    const float* Q  = (const float*)d_in[0];
    const float* K  = (const float*)d_in[1];
    const float* V  = (const float*)d_in[2];
    const float* Wq = (const float*)d_in[3];
    const float* bq = (const float*)d_in[4];
    const float* Wk = (const float*)d_in[5];
    const float* bk = (const float*)d_in[6];
    const float* Wv = (const float*)d_in[7];
    const float* bv = (const float*)d_in[8];
    const float* Wo = (const float*)d_in[9];
    const float* bo = (const float*)d_in[10];

    float* out = (float*)d_out;
    const long long OUT_ELEMS  = (long long)BB * TT * DM;
    const long long ATTN_ELEMS = (long long)NBH * TT * TT;

    float *q, *k, *v, *ctx, *attn, *rmax, *rsum;
    { void* p; cudaGetSymbolAddress(&p, g_q);      q    = (float*)p; }
    { void* p; cudaGetSymbolAddress(&p, g_k);      k    = (float*)p; }
    { void* p; cudaGetSymbolAddress(&p, g_v);      v    = (float*)p; }
    { void* p; cudaGetSymbolAddress(&p, g_ctx);    ctx  = (float*)p; }
    { void* p; cudaGetSymbolAddress(&p, g_rowmax); rmax = (float*)p; }
    { void* p; cudaGetSymbolAddress(&p, g_rowsum); rsum = (float*)p; }
    if ((long long)out_size >= OUT_ELEMS + ATTN_ELEMS) {
        attn = out + OUT_ELEMS;
    } else {
        void* p; cudaGetSymbolAddress(&p, g_attn_fb); attn = (float*)p;
    }

    cudaFuncSetAttribute(proj_mma,   cudaFuncAttributeMaxDynamicSharedMemorySize, PJ_SMEM_BYTES);
    cudaFuncSetAttribute(scores_mma, cudaFuncAttributeMaxDynamicSharedMemorySize, SC_SMEM_BYTES);
    cudaFuncSetAttribute(ctx_mma,    cudaFuncAttributeMaxDynamicSharedMemorySize, CT_SMEM_BYTES);

    dim3 gp(DM / 128, MROWS / 128);   // (4, 64)
    proj_mma<<<gp, 512, PJ_SMEM_BYTES>>>(Q, Wq, bq, q, 0);
    proj_mma<<<gp, 512, PJ_SMEM_BYTES>>>(K, Wk, bk, k, 0);
    proj_mma<<<gp, 512, PJ_SMEM_BYTES>>>(V, Wv, bv, v, 0);

    dim3 gs(TT / 128, NBH);           // (16, 32)
    scores_mma<<<gs, 512, SC_SMEM_BYTES>>>(q, k, attn, rmax, rsum);
    ctx_mma<<<gs, 512, CT_SMEM_BYTES>>>(attn, v, ctx, rmax, rsum);

    proj_mma<<<gp, 512, PJ_SMEM_BYTES>>>(ctx, Wo, bo, out, 1);
}